// round 6
// baseline (speedup 1.0000x reference)
#include <cuda_runtime.h>
#include <cuda_fp16.h>
#include <cstdint>

// GRU cell B=8192, I=H=1024 fp32. mma.sync fp16 m16n8k16 (fp32 accum),
// pre-converted fragment-permuted operands. 4 warps/CTA, 32 MMAs per warp
// per k16-step => 1.0 smem wavefront per MMA. R6: fixed tail under-wait
// (drain iterations use wait_group 0; R5 read the final stage while in flight).
//   prep:  fp16+permute x,h -> g_xp,g_hp ; 6 weights -> g_Wh[]
//   zr:    block 128x64 dual-acc: z -> g_Z (f32), rh -> g_rhp (fp16 frag)
//   ht:    block 128x128: out = z*h + (1-z)*tanh(rh Wu^T + x Ww^T)

#define BB 8192
#define HH 1024
#define KK 1024

// Fragment layouts (validated R4):
//  A: g_ap[((rb*64+kb)*32+lane)] = uint4{a0,a1,a2,a3}, lane=g*4+tq
//   a0={A[16rb+g][16kb+tq*2],+1} a1=row+8  a2=col+8  a3=row+8,col+8
//  B: g_Wh[w][((nb*64+kb)*32+lane)] = uint2{b0,b1}
//   b0={W[8nb+g][16kb+tq*2],+1}  b1={W[8nb+g][16kb+8+tq*2],+1}
__device__ __align__(16) uint4 g_xp[BB * KK / 8];
__device__ __align__(16) uint4 g_hp[BB * KK / 8];
__device__ __align__(16) uint4 g_rhp[BB * KK / 8];
__device__ __align__(16) float g_Z[BB * HH];
__device__ __align__(16) uint2 g_Wh[6][HH * KK / 4];  // 0:Wwz 1:Wuz 2:Wwr 3:Wur 4:Wu 5:Ww

__device__ __forceinline__ void cp_async16(void* sdst, const void* gsrc) {
    uint32_t s = (uint32_t)__cvta_generic_to_shared(sdst);
    asm volatile("cp.async.cg.shared.global [%0], [%1], 16;\n" :: "r"(s), "l"(gsrc));
}
__device__ __forceinline__ void cp_commit() { asm volatile("cp.async.commit_group;\n"); }
__device__ __forceinline__ void cp_wait1() { asm volatile("cp.async.wait_group 1;\n"); }
__device__ __forceinline__ void cp_wait0() { asm volatile("cp.async.wait_group 0;\n"); }

__device__ __forceinline__ void mma16(float c[4], const uint4& a, const uint2& b) {
    asm volatile(
        "mma.sync.aligned.m16n8k16.row.col.f32.f16.f16.f32 "
        "{%0,%1,%2,%3},{%4,%5,%6,%7},{%8,%9},{%0,%1,%2,%3};\n"
        : "+f"(c[0]), "+f"(c[1]), "+f"(c[2]), "+f"(c[3])
        : "r"(a.x), "r"(a.y), "r"(a.z), "r"(a.w), "r"(b.x), "r"(b.y));
}
__device__ __forceinline__ float sig_(float v) { return 1.0f / (1.0f + __expf(-v)); }
__device__ __forceinline__ uint32_t h2u(float a, float b) {
    __half2 h = __floats2half2_rn(a, b);
    return *reinterpret_cast<uint32_t*>(&h);
}

// ---------------------------------------------------------------------------
// Preprocess (unchanged, validated R4)
// ---------------------------------------------------------------------------
__global__ void __launch_bounds__(256) permA(const float* __restrict__ x,
                                             const float* __restrict__ hm) {
    const float* src = blockIdx.y ? hm : x;
    uint4* dst = blockIdx.y ? g_hp : g_xp;
    int t = blockIdx.x * 256 + threadIdx.x;
    int lane = t & 31, kb = (t >> 5) & 63, rb = t >> 11;
    int g = lane >> 2, tq = lane & 3;
    const float* s = src + (rb * 16 + g) * KK + kb * 16 + tq * 2;
    float2 v00 = *reinterpret_cast<const float2*>(s);
    float2 v10 = *reinterpret_cast<const float2*>(s + 8 * KK);
    float2 v01 = *reinterpret_cast<const float2*>(s + 8);
    float2 v11 = *reinterpret_cast<const float2*>(s + 8 * KK + 8);
    uint4 o;
    o.x = h2u(v00.x, v00.y);
    o.y = h2u(v10.x, v10.y);
    o.z = h2u(v01.x, v01.y);
    o.w = h2u(v11.x, v11.y);
    dst[t] = o;
}

__global__ void __launch_bounds__(256) permB(
    const float* __restrict__ w0, const float* __restrict__ w1,
    const float* __restrict__ w2, const float* __restrict__ w3,
    const float* __restrict__ w4, const float* __restrict__ w5) {
    const float* srcs[6] = {w0, w1, w2, w3, w4, w5};
    const float* src = srcs[blockIdx.y];
    uint2* dst = g_Wh[blockIdx.y];
    int t = blockIdx.x * 256 + threadIdx.x;
    int lane = t & 31, kb = (t >> 5) & 63, nb = t >> 11;
    int g = lane >> 2, tq = lane & 3;
    const float* s = src + (nb * 8 + g) * KK + kb * 16 + tq * 2;
    float2 v0 = *reinterpret_cast<const float2*>(s);
    float2 v1 = *reinterpret_cast<const float2*>(s + 8);
    uint2 o;
    o.x = h2u(v0.x, v0.y);
    o.y = h2u(v1.x, v1.y);
    dst[t] = o;
}

// ---------------------------------------------------------------------------
// Kernel 1: dual-acc z/r GEMM. Block 128x64, 4 warps (warp 64x32 dual), BK=32.
// smem per buf (uint4): A[0,512) Bz[512,768) Br[768,1024). 3 bufs = 48KB.
// ---------------------------------------------------------------------------
__global__ void __launch_bounds__(128, 2) gemm_zr(const float* __restrict__ h) {
    extern __shared__ uint4 sm4[];
    const int tid = threadIdx.x, wid = tid >> 5, lane = tid & 31;
    const int g = lane >> 2, tq = lane & 3;
    const int mrow = wid & 1, ncol = wid >> 1;
    const int bm = blockIdx.x * 128, bn = blockIdx.y * 64;
    const int rb0 = bm >> 4, nb0 = bn >> 3;

    auto stage = [&](int t, int buf) {
        const int seg = t >> 5, kb0 = (t & 31) * 2;
        const uint4* Ag = seg ? g_hp : g_xp;
        const uint4* Bz = reinterpret_cast<const uint4*>(g_Wh[seg ? 1 : 0]);
        const uint4* Br = reinterpret_cast<const uint4*>(g_Wh[seg ? 3 : 2]);
        uint4* dst = &sm4[buf * 1024];
        #pragma unroll
        for (int i = 0; i < 4; i++) {
            int c = tid + i * 128;                       // 512 uint4 of A
            int rbl = c >> 6, kk = (c >> 5) & 1, ln = c & 31;
            cp_async16(&dst[c], &Ag[((rb0 + rbl) * 64 + kb0 + kk) * 32 + ln]);
        }
        #pragma unroll
        for (int i = 0; i < 2; i++) {
            int c = tid + i * 128;                       // 256 uint4 each
            int nbl = c >> 5, kk = (c >> 4) & 1, pr = c & 15;
            int so = ((nb0 + nbl) * 64 + kb0 + kk) * 16 + pr;
            cp_async16(&dst[512 + c], &Bz[so]);
            cp_async16(&dst[768 + c], &Br[so]);
        }
        cp_commit();
    };

    float accZ[4][4][4] = {}, accR[4][4][4] = {};
    stage(0, 0);
    stage(1, 1);

    for (int t = 0; t < 64; t++) {
        if (t + 2 < 64) cp_wait1(); else cp_wait0();   // drain: full wait (R5 bug fix)
        __syncthreads();
        if (t + 2 < 64) stage(t + 2, (t + 2) % 3);
        const uint4* buf = &sm4[(t % 3) * 1024];
        const uint2* Bz_ = reinterpret_cast<const uint2*>(&buf[512]);
        const uint2* Br_ = reinterpret_cast<const uint2*>(&buf[768]);
        #pragma unroll
        for (int kk = 0; kk < 2; kk++) {
            uint4 a[4];
            #pragma unroll
            for (int r = 0; r < 4; r++)
                a[r] = buf[((mrow * 4 + r) * 2 + kk) * 32 + lane];
            #pragma unroll
            for (int n = 0; n < 4; n++) {
                uint2 bz = Bz_[((ncol * 4 + n) * 2 + kk) * 32 + lane];
                uint2 br = Br_[((ncol * 4 + n) * 2 + kk) * 32 + lane];
                #pragma unroll
                for (int r = 0; r < 4; r++) {
                    mma16(accZ[r][n], a[r], bz);
                    mma16(accR[r][n], a[r], br);
                }
            }
        }
    }

    // epilogue: z f32; rh fp16 fragment-ordered
    uint32_t* rhp32 = reinterpret_cast<uint32_t*>(g_rhp);
    #pragma unroll
    for (int r = 0; r < 4; r++) {
        const int rowbase = bm + mrow * 64 + r * 16;
        const int rbg = rowbase >> 4;
        #pragma unroll
        for (int n = 0; n < 4; n++) {
            const int col = bn + ncol * 32 + n * 8 + tq * 2;
            const int kb = (bn >> 4) + ncol * 2 + (n >> 1);
            #pragma unroll
            for (int half = 0; half < 2; half++) {
                const int row = rowbase + half * 8 + g;
                const int idx = row * HH + col;
                float2 hv = *reinterpret_cast<const float2*>(&h[idx]);
                float2 zo;
                zo.x = sig_(accZ[r][n][half * 2]);
                zo.y = sig_(accZ[r][n][half * 2 + 1]);
                *reinterpret_cast<float2*>(&g_Z[idx]) = zo;
                float rh0 = sig_(accR[r][n][half * 2]) * hv.x;
                float rh1 = sig_(accR[r][n][half * 2 + 1]) * hv.y;
                const int comp = half + 2 * (n & 1);
                rhp32[((rbg * 64 + kb) * 32 + lane) * 4 + comp] = h2u(rh0, rh1);
            }
        }
    }
}

// ---------------------------------------------------------------------------
// Kernel 2: block 128x128, 4 warps (warp 64x64), BK=32.
// smem per buf (uint4): A[0,512) B[512,1024). 3 bufs = 48KB.
// ---------------------------------------------------------------------------
__global__ void __launch_bounds__(128, 2) gemm_ht(const float* __restrict__ h,
                                                  float* __restrict__ out) {
    extern __shared__ uint4 sm4[];
    const int tid = threadIdx.x, wid = tid >> 5, lane = tid & 31;
    const int g = lane >> 2, tq = lane & 3;
    const int mrow = wid & 1, ncol = wid >> 1;
    const int bm = blockIdx.x * 128, bn = blockIdx.y * 128;
    const int rb0 = bm >> 4, nb0 = bn >> 3;

    auto stage = [&](int t, int buf) {
        const int seg = t >> 5, kb0 = (t & 31) * 2;
        const uint4* Ag = seg ? g_xp : g_rhp;
        const uint4* Bg = reinterpret_cast<const uint4*>(g_Wh[seg ? 5 : 4]);
        uint4* dst = &sm4[buf * 1024];
        #pragma unroll
        for (int i = 0; i < 4; i++) {
            int c = tid + i * 128;
            int rbl = c >> 6, kk = (c >> 5) & 1, ln = c & 31;
            cp_async16(&dst[c], &Ag[((rb0 + rbl) * 64 + kb0 + kk) * 32 + ln]);
        }
        #pragma unroll
        for (int i = 0; i < 4; i++) {
            int c = tid + i * 128;                       // 512 uint4 of B
            int nbl = c >> 5, kk = (c >> 4) & 1, pr = c & 15;
            cp_async16(&dst[512 + c], &Bg[((nb0 + nbl) * 64 + kb0 + kk) * 16 + pr]);
        }
        cp_commit();
    };

    float acc[4][8][4] = {};
    stage(0, 0);
    stage(1, 1);

    for (int t = 0; t < 64; t++) {
        if (t + 2 < 64) cp_wait1(); else cp_wait0();   // drain: full wait (R5 bug fix)
        __syncthreads();
        if (t + 2 < 64) stage(t + 2, (t + 2) % 3);
        const uint4* buf = &sm4[(t % 3) * 1024];
        const uint2* B_ = reinterpret_cast<const uint2*>(&buf[512]);
        #pragma unroll
        for (int kk = 0; kk < 2; kk++) {
            uint4 a[4];
            #pragma unroll
            for (int r = 0; r < 4; r++)
                a[r] = buf[((mrow * 4 + r) * 2 + kk) * 32 + lane];
            #pragma unroll
            for (int n = 0; n < 8; n++) {
                uint2 b = B_[((ncol * 8 + n) * 2 + kk) * 32 + lane];
                #pragma unroll
                for (int r = 0; r < 4; r++)
                    mma16(acc[r][n], a[r], b);
            }
        }
    }

    #pragma unroll
    for (int r = 0; r < 4; r++) {
        const int rowbase = bm + mrow * 64 + r * 16;
        #pragma unroll
        for (int n = 0; n < 8; n++) {
            const int col = bn + ncol * 64 + n * 8 + tq * 2;
            #pragma unroll
            for (int half = 0; half < 2; half++) {
                const int idx = (rowbase + half * 8 + g) * HH + col;
                float2 hv = *reinterpret_cast<const float2*>(&h[idx]);
                float2 zv = *reinterpret_cast<const float2*>(&g_Z[idx]);
                float2 ov;
                ov.x = zv.x * hv.x + (1.0f - zv.x) * tanhf(acc[r][n][half * 2]);
                ov.y = zv.y * hv.y + (1.0f - zv.y) * tanhf(acc[r][n][half * 2 + 1]);
                *reinterpret_cast<float2*>(&out[idx]) = ov;
            }
        }
    }
}

// ---------------------------------------------------------------------------
extern "C" void kernel_launch(void* const* d_in, const int* in_sizes, int n_in,
                              void* d_out, int out_size) {
    const float* x   = (const float*)d_in[0];
    const float* h   = (const float*)d_in[1];
    const float* Wwz = (const float*)d_in[2];
    const float* Wuz = (const float*)d_in[3];
    const float* Wwr = (const float*)d_in[4];
    const float* Wur = (const float*)d_in[5];
    const float* Wu  = (const float*)d_in[6];
    const float* Ww  = (const float*)d_in[7];
    float* out = (float*)d_out;

    const int smem = 3 * 1024 * 16;   // 48 KB
    cudaFuncSetAttribute(gemm_zr, cudaFuncAttributeMaxDynamicSharedMemorySize, smem);
    cudaFuncSetAttribute(gemm_ht, cudaFuncAttributeMaxDynamicSharedMemorySize, smem);

    permA<<<dim3(4096, 2), 256>>>(x, h);
    permB<<<dim3(1024, 6), 256>>>(Wwz, Wuz, Wwr, Wur, Wu, Ww);
    gemm_zr<<<dim3(64, 16), 128, smem>>>(h);
    gemm_ht<<<dim3(64, 8), 128, smem>>>(h, out);
}

// round 7
// speedup vs baseline: 1.1608x; 1.1608x over previous
#include <cuda_runtime.h>
#include <cuda_fp16.h>
#include <cstdint>

// GRU cell B=8192, I=H=1024 fp32. mma.sync fp16 m16n8k16 (fp32 accum).
// R7: zr reverted to proven R4 config (16 warps/SM, 192B/MMA);
//     ht retiled to block 128x128, warp 64x32 (192B/MMA) at 16 warps/SM
//     (R6 showed 8 warps/SM is latency-bound regardless of smem efficiency).

#define BB 8192
#define HH 1024
#define KK 1024

// Fragment layouts (validated R4):
//  A: g_ap[((rb*64+kb)*32+lane)] = uint4{a0,a1,a2,a3}, lane=g*4+tq
//  B: g_Wh[w][((nb*64+kb)*32+lane)] = uint2{b0,b1}
__device__ __align__(16) uint4 g_xp[BB * KK / 8];
__device__ __align__(16) uint4 g_hp[BB * KK / 8];
__device__ __align__(16) uint4 g_rhp[BB * KK / 8];
__device__ __align__(16) float g_Z[BB * HH];
__device__ __align__(16) uint2 g_Wh[6][HH * KK / 4];  // 0:Wwz 1:Wuz 2:Wwr 3:Wur 4:Wu 5:Ww

__device__ __forceinline__ void cp_async16(void* sdst, const void* gsrc) {
    uint32_t s = (uint32_t)__cvta_generic_to_shared(sdst);
    asm volatile("cp.async.cg.shared.global [%0], [%1], 16;\n" :: "r"(s), "l"(gsrc));
}
__device__ __forceinline__ void cp_commit() { asm volatile("cp.async.commit_group;\n"); }
__device__ __forceinline__ void cp_wait_all() { asm volatile("cp.async.wait_group 0;\n"); }

__device__ __forceinline__ void mma16(float c[4], const uint4& a, const uint2& b) {
    asm volatile(
        "mma.sync.aligned.m16n8k16.row.col.f32.f16.f16.f32 "
        "{%0,%1,%2,%3},{%4,%5,%6,%7},{%8,%9},{%0,%1,%2,%3};\n"
        : "+f"(c[0]), "+f"(c[1]), "+f"(c[2]), "+f"(c[3])
        : "r"(a.x), "r"(a.y), "r"(a.z), "r"(a.w), "r"(b.x), "r"(b.y));
}
__device__ __forceinline__ float sig_(float v) { return 1.0f / (1.0f + __expf(-v)); }
__device__ __forceinline__ uint32_t h2u(float a, float b) {
    __half2 h = __floats2half2_rn(a, b);
    return *reinterpret_cast<uint32_t*>(&h);
}

// ---------------------------------------------------------------------------
// Preprocess (validated R4)
// ---------------------------------------------------------------------------
__global__ void __launch_bounds__(256) permA(const float* __restrict__ x,
                                             const float* __restrict__ hm) {
    const float* src = blockIdx.y ? hm : x;
    uint4* dst = blockIdx.y ? g_hp : g_xp;
    int t = blockIdx.x * 256 + threadIdx.x;
    int lane = t & 31, kb = (t >> 5) & 63, rb = t >> 11;
    int g = lane >> 2, tq = lane & 3;
    const float* s = src + (rb * 16 + g) * KK + kb * 16 + tq * 2;
    float2 v00 = *reinterpret_cast<const float2*>(s);
    float2 v10 = *reinterpret_cast<const float2*>(s + 8 * KK);
    float2 v01 = *reinterpret_cast<const float2*>(s + 8);
    float2 v11 = *reinterpret_cast<const float2*>(s + 8 * KK + 8);
    uint4 o;
    o.x = h2u(v00.x, v00.y);
    o.y = h2u(v10.x, v10.y);
    o.z = h2u(v01.x, v01.y);
    o.w = h2u(v11.x, v11.y);
    dst[t] = o;
}

__global__ void __launch_bounds__(256) permB(
    const float* __restrict__ w0, const float* __restrict__ w1,
    const float* __restrict__ w2, const float* __restrict__ w3,
    const float* __restrict__ w4, const float* __restrict__ w5) {
    const float* srcs[6] = {w0, w1, w2, w3, w4, w5};
    const float* src = srcs[blockIdx.y];
    uint2* dst = g_Wh[blockIdx.y];
    int t = blockIdx.x * 256 + threadIdx.x;
    int lane = t & 31, kb = (t >> 5) & 63, nb = t >> 11;
    int g = lane >> 2, tq = lane & 3;
    const float* s = src + (nb * 8 + g) * KK + kb * 16 + tq * 2;
    float2 v0 = *reinterpret_cast<const float2*>(s);
    float2 v1 = *reinterpret_cast<const float2*>(s + 8);
    uint2 o;
    o.x = h2u(v0.x, v0.y);
    o.y = h2u(v1.x, v1.y);
    dst[t] = o;
}

// ---------------------------------------------------------------------------
// Kernel 1 (R4 verbatim): dual-acc z/r GEMM. Block 128x64, 8 warps (4m x 2n),
// warp 32x32 dual, BK=64. smem: A 2x1024 | Bz 2x512 | Br 2x512 uint4 = 64KB.
// ---------------------------------------------------------------------------
__global__ void __launch_bounds__(256, 2) gemm_zr(const float* __restrict__ h) {
    extern __shared__ uint4 sm4[];
    const int tid = threadIdx.x, wid = tid >> 5, lane = tid & 31;
    const int g = lane >> 2, tq = lane & 3;
    const int bm = blockIdx.x * 128, bn = blockIdx.y * 64;
    const int rb0 = bm >> 4, nb0 = bn >> 3;

    auto stage = [&](int t, int buf) {
        const int seg = t >> 4, kb = (t & 15) * 4;
        const uint4* Ag = seg ? g_hp : g_xp;
        const uint4* Bz = reinterpret_cast<const uint4*>(g_Wh[seg ? 1 : 0]);
        const uint4* Br = reinterpret_cast<const uint4*>(g_Wh[seg ? 3 : 2]);
        #pragma unroll
        for (int i = 0; i < 4; i++) {
            int c = tid + i * 256, rbl = c >> 7, rem = c & 127;
            cp_async16(&sm4[buf * 1024 + rbl * 128 + rem],
                       &Ag[((rb0 + rbl) * 64 + kb) * 32 + rem]);
        }
        #pragma unroll
        for (int i = 0; i < 2; i++) {
            int c = tid + i * 256, nbl = c >> 6, rem = c & 63;
            int so = ((nb0 + nbl) * 64 + kb) * 16 + rem;
            cp_async16(&sm4[2048 + buf * 512 + nbl * 64 + rem], &Bz[so]);
            cp_async16(&sm4[3072 + buf * 512 + nbl * 64 + rem], &Br[so]);
        }
        cp_commit();
    };

    float accZ[2][4][4] = {}, accR[2][4][4] = {};
    stage(0, 0);

    const int r0 = (wid & 3) * 2, nbl = (wid >> 2) * 4;
    for (int t = 0; t < 32; t++) {
        cp_wait_all();
        __syncthreads();
        if (t + 1 < 32) stage(t + 1, (t + 1) & 1);
        const int buf = t & 1;
        const uint4* A_ = &sm4[buf * 1024];
        const uint2* Bz_ = reinterpret_cast<const uint2*>(&sm4[2048 + buf * 512]);
        const uint2* Br_ = reinterpret_cast<const uint2*>(&sm4[3072 + buf * 512]);
        #pragma unroll
        for (int kk = 0; kk < 4; kk++) {
            uint4 a0 = A_[(r0 * 4 + kk) * 32 + lane];
            uint4 a1 = A_[((r0 + 1) * 4 + kk) * 32 + lane];
            #pragma unroll
            for (int nt = 0; nt < 4; nt++) {
                uint2 bz = Bz_[(nbl + nt) * 128 + kk * 32 + lane];
                uint2 br = Br_[(nbl + nt) * 128 + kk * 32 + lane];
                mma16(accZ[0][nt], a0, bz);
                mma16(accZ[1][nt], a1, bz);
                mma16(accR[0][nt], a0, br);
                mma16(accR[1][nt], a1, br);
            }
        }
        __syncthreads();
    }

    // epilogue (R4): z f32; rh fp16 fragment-ordered
    uint32_t* rhp32 = reinterpret_cast<uint32_t*>(g_rhp);
    const int wm = (wid & 3) * 32, wn = (wid >> 2) * 32;
    #pragma unroll
    for (int mt = 0; mt < 2; mt++) {
        const int rbase = bm + wm + mt * 16;
        #pragma unroll
        for (int nt = 0; nt < 4; nt++) {
            const int colb = bn + wn + nt * 8 + tq * 2;
            const int kb = ((bn + wn) >> 4) + (nt >> 1);
            #pragma unroll
            for (int half = 0; half < 2; half++) {
                const int row = rbase + half * 8 + g;
                const int idx = row * HH + colb;
                float2 hv = *reinterpret_cast<const float2*>(&h[idx]);
                float2 zo;
                zo.x = sig_(accZ[mt][nt][half * 2]);
                zo.y = sig_(accZ[mt][nt][half * 2 + 1]);
                *reinterpret_cast<float2*>(&g_Z[idx]) = zo;
                float rh0 = sig_(accR[mt][nt][half * 2]) * hv.x;
                float rh1 = sig_(accR[mt][nt][half * 2 + 1]) * hv.y;
                const int rbm = (rbase >> 4);
                const int regidx = half + 2 * (nt & 1);
                rhp32[((rbm * 64 + kb) * 32 + lane) * 4 + regidx] = h2u(rh0, rh1);
            }
        }
    }
}

// ---------------------------------------------------------------------------
// Kernel 2 (new): block 128x128, 8 warps (2m x 4n), warp 64x32, BK=64.
// smem per buf (uint4): A[0,1024) B[1024,2048). 2 bufs = 64KB.
// ---------------------------------------------------------------------------
__global__ void __launch_bounds__(256, 2) gemm_ht(const float* __restrict__ h,
                                                  float* __restrict__ out) {
    extern __shared__ uint4 sm4[];
    const int tid = threadIdx.x, wid = tid >> 5, lane = tid & 31;
    const int g = lane >> 2, tq = lane & 3;
    const int mrow = wid & 1, ncol = wid >> 1;   // 2 x 4 warps
    const int bm = blockIdx.x * 128, bn = blockIdx.y * 128;
    const int rb0 = bm >> 4, nb0 = bn >> 3;

    auto stage = [&](int t, int buf) {
        const int seg = t >> 4, kb0 = (t & 15) * 4;
        const uint4* Ag = seg ? g_xp : g_rhp;
        const uint4* Bg = reinterpret_cast<const uint4*>(g_Wh[seg ? 5 : 4]);
        uint4* dst = &sm4[buf * 2048];
        #pragma unroll
        for (int i = 0; i < 4; i++) {
            int c = tid + i * 256, rbl = c >> 7, rem = c & 127;
            cp_async16(&dst[c], &Ag[((rb0 + rbl) * 64 + kb0) * 32 + rem]);
        }
        #pragma unroll
        for (int i = 0; i < 4; i++) {
            int c = tid + i * 256, nb = c >> 6, rem = c & 63;
            cp_async16(&dst[1024 + c], &Bg[((nb0 + nb) * 64 + kb0) * 16 + rem]);
        }
        cp_commit();
    };

    float acc[4][4][4] = {};
    stage(0, 0);

    for (int t = 0; t < 32; t++) {
        cp_wait_all();
        __syncthreads();
        if (t + 1 < 32) stage(t + 1, (t + 1) & 1);
        const uint4* A_ = &sm4[(t & 1) * 2048];
        const uint2* B_ = reinterpret_cast<const uint2*>(&sm4[(t & 1) * 2048 + 1024]);
        #pragma unroll
        for (int kk = 0; kk < 4; kk++) {
            uint4 a[4];
            #pragma unroll
            for (int r = 0; r < 4; r++)
                a[r] = A_[((mrow * 4 + r) * 4 + kk) * 32 + lane];
            #pragma unroll
            for (int n = 0; n < 4; n++) {
                uint2 b = B_[((ncol * 4 + n) * 4 + kk) * 32 + lane];
                #pragma unroll
                for (int r = 0; r < 4; r++)
                    mma16(acc[r][n], a[r], b);
            }
        }
        __syncthreads();
    }

    #pragma unroll
    for (int r = 0; r < 4; r++) {
        const int rowbase = bm + mrow * 64 + r * 16;
        #pragma unroll
        for (int n = 0; n < 4; n++) {
            const int col = bn + ncol * 32 + n * 8 + tq * 2;
            #pragma unroll
            for (int half = 0; half < 2; half++) {
                const int idx = (rowbase + half * 8 + g) * HH + col;
                float2 hv = *reinterpret_cast<const float2*>(&h[idx]);
                float2 zv = *reinterpret_cast<const float2*>(&g_Z[idx]);
                float2 ov;
                ov.x = zv.x * hv.x + (1.0f - zv.x) * tanhf(acc[r][n][half * 2]);
                ov.y = zv.y * hv.y + (1.0f - zv.y) * tanhf(acc[r][n][half * 2 + 1]);
                *reinterpret_cast<float2*>(&out[idx]) = ov;
            }
        }
    }
}

// ---------------------------------------------------------------------------
extern "C" void kernel_launch(void* const* d_in, const int* in_sizes, int n_in,
                              void* d_out, int out_size) {
    const float* x   = (const float*)d_in[0];
    const float* h   = (const float*)d_in[1];
    const float* Wwz = (const float*)d_in[2];
    const float* Wuz = (const float*)d_in[3];
    const float* Wwr = (const float*)d_in[4];
    const float* Wur = (const float*)d_in[5];
    const float* Wu  = (const float*)d_in[6];
    const float* Ww  = (const float*)d_in[7];
    float* out = (float*)d_out;

    const int s1 = 4096 * 16;   // 64 KB
    const int s2 = 4096 * 16;   // 64 KB
    cudaFuncSetAttribute(gemm_zr, cudaFuncAttributeMaxDynamicSharedMemorySize, s1);
    cudaFuncSetAttribute(gemm_ht, cudaFuncAttributeMaxDynamicSharedMemorySize, s2);

    permA<<<dim3(4096, 2), 256>>>(x, h);
    permB<<<dim3(1024, 6), 256>>>(Wwz, Wuz, Wwr, Wur, Wu, Ww);
    gemm_zr<<<dim3(64, 16), 256, s1>>>(h);
    gemm_ht<<<dim3(64, 8), 256, s2>>>(h, out);
}

// round 8
// speedup vs baseline: 1.1956x; 1.0300x over previous
#include <cuda_runtime.h>
#include <cuda_fp16.h>
#include <cstdint>

// GRU cell B=8192, I=H=1024 fp32. mma.sync fp16 m16n8k16 (fp32 accum).
// R8: ht retiled to 24 warps/SM (3 CTAs x 8 warps, warp 32x32, block 128x64)
//     to break the LDS/MMA phase-lock seen at 16 warps/SM. zr = R7 verbatim.

#define BB 8192
#define HH 1024
#define KK 1024

// Fragment layouts (validated R4):
//  A: g_ap[((rb*64+kb)*32+lane)] = uint4{a0,a1,a2,a3}, lane=g*4+tq
//  B: g_Wh[w][((nb*64+kb)*32+lane)] = uint2{b0,b1}
__device__ __align__(16) uint4 g_xp[BB * KK / 8];
__device__ __align__(16) uint4 g_hp[BB * KK / 8];
__device__ __align__(16) uint4 g_rhp[BB * KK / 8];
__device__ __align__(16) float g_Z[BB * HH];
__device__ __align__(16) uint2 g_Wh[6][HH * KK / 4];  // 0:Wwz 1:Wuz 2:Wwr 3:Wur 4:Wu 5:Ww

__device__ __forceinline__ void cp_async16(void* sdst, const void* gsrc) {
    uint32_t s = (uint32_t)__cvta_generic_to_shared(sdst);
    asm volatile("cp.async.cg.shared.global [%0], [%1], 16;\n" :: "r"(s), "l"(gsrc));
}
__device__ __forceinline__ void cp_commit() { asm volatile("cp.async.commit_group;\n"); }
__device__ __forceinline__ void cp_wait_all() { asm volatile("cp.async.wait_group 0;\n"); }

__device__ __forceinline__ void mma16(float c[4], const uint4& a, const uint2& b) {
    asm volatile(
        "mma.sync.aligned.m16n8k16.row.col.f32.f16.f16.f32 "
        "{%0,%1,%2,%3},{%4,%5,%6,%7},{%8,%9},{%0,%1,%2,%3};\n"
        : "+f"(c[0]), "+f"(c[1]), "+f"(c[2]), "+f"(c[3])
        : "r"(a.x), "r"(a.y), "r"(a.z), "r"(a.w), "r"(b.x), "r"(b.y));
}
__device__ __forceinline__ float sig_(float v) { return 1.0f / (1.0f + __expf(-v)); }
__device__ __forceinline__ float ftanh_(float v) {
    return 1.0f - 2.0f / (1.0f + __expf(2.0f * v));
}
__device__ __forceinline__ uint32_t h2u(float a, float b) {
    __half2 h = __floats2half2_rn(a, b);
    return *reinterpret_cast<uint32_t*>(&h);
}

// ---------------------------------------------------------------------------
// Preprocess (validated R4)
// ---------------------------------------------------------------------------
__global__ void __launch_bounds__(256) permA(const float* __restrict__ x,
                                             const float* __restrict__ hm) {
    const float* src = blockIdx.y ? hm : x;
    uint4* dst = blockIdx.y ? g_hp : g_xp;
    int t = blockIdx.x * 256 + threadIdx.x;
    int lane = t & 31, kb = (t >> 5) & 63, rb = t >> 11;
    int g = lane >> 2, tq = lane & 3;
    const float* s = src + (rb * 16 + g) * KK + kb * 16 + tq * 2;
    float2 v00 = *reinterpret_cast<const float2*>(s);
    float2 v10 = *reinterpret_cast<const float2*>(s + 8 * KK);
    float2 v01 = *reinterpret_cast<const float2*>(s + 8);
    float2 v11 = *reinterpret_cast<const float2*>(s + 8 * KK + 8);
    uint4 o;
    o.x = h2u(v00.x, v00.y);
    o.y = h2u(v10.x, v10.y);
    o.z = h2u(v01.x, v01.y);
    o.w = h2u(v11.x, v11.y);
    dst[t] = o;
}

__global__ void __launch_bounds__(256) permB(
    const float* __restrict__ w0, const float* __restrict__ w1,
    const float* __restrict__ w2, const float* __restrict__ w3,
    const float* __restrict__ w4, const float* __restrict__ w5) {
    const float* srcs[6] = {w0, w1, w2, w3, w4, w5};
    const float* src = srcs[blockIdx.y];
    uint2* dst = g_Wh[blockIdx.y];
    int t = blockIdx.x * 256 + threadIdx.x;
    int lane = t & 31, kb = (t >> 5) & 63, nb = t >> 11;
    int g = lane >> 2, tq = lane & 3;
    const float* s = src + (nb * 8 + g) * KK + kb * 16 + tq * 2;
    float2 v0 = *reinterpret_cast<const float2*>(s);
    float2 v1 = *reinterpret_cast<const float2*>(s + 8);
    uint2 o;
    o.x = h2u(v0.x, v0.y);
    o.y = h2u(v1.x, v1.y);
    dst[t] = o;
}

// ---------------------------------------------------------------------------
// Kernel 1 (R7/R4 verbatim): dual-acc z/r GEMM. Block 128x64, 8 warps (4m x 2n),
// warp 32x32 dual, BK=64. smem: A 2x1024 | Bz 2x512 | Br 2x512 uint4 = 64KB.
// ---------------------------------------------------------------------------
__global__ void __launch_bounds__(256, 2) gemm_zr(const float* __restrict__ h) {
    extern __shared__ uint4 sm4[];
    const int tid = threadIdx.x, wid = tid >> 5, lane = tid & 31;
    const int g = lane >> 2, tq = lane & 3;
    const int bm = blockIdx.x * 128, bn = blockIdx.y * 64;
    const int rb0 = bm >> 4, nb0 = bn >> 3;

    auto stage = [&](int t, int buf) {
        const int seg = t >> 4, kb = (t & 15) * 4;
        const uint4* Ag = seg ? g_hp : g_xp;
        const uint4* Bz = reinterpret_cast<const uint4*>(g_Wh[seg ? 1 : 0]);
        const uint4* Br = reinterpret_cast<const uint4*>(g_Wh[seg ? 3 : 2]);
        #pragma unroll
        for (int i = 0; i < 4; i++) {
            int c = tid + i * 256, rbl = c >> 7, rem = c & 127;
            cp_async16(&sm4[buf * 1024 + rbl * 128 + rem],
                       &Ag[((rb0 + rbl) * 64 + kb) * 32 + rem]);
        }
        #pragma unroll
        for (int i = 0; i < 2; i++) {
            int c = tid + i * 256, nbl = c >> 6, rem = c & 63;
            int so = ((nb0 + nbl) * 64 + kb) * 16 + rem;
            cp_async16(&sm4[2048 + buf * 512 + nbl * 64 + rem], &Bz[so]);
            cp_async16(&sm4[3072 + buf * 512 + nbl * 64 + rem], &Br[so]);
        }
        cp_commit();
    };

    float accZ[2][4][4] = {}, accR[2][4][4] = {};
    stage(0, 0);

    const int r0 = (wid & 3) * 2, nbl = (wid >> 2) * 4;
    for (int t = 0; t < 32; t++) {
        cp_wait_all();
        __syncthreads();
        if (t + 1 < 32) stage(t + 1, (t + 1) & 1);
        const int buf = t & 1;
        const uint4* A_ = &sm4[buf * 1024];
        const uint2* Bz_ = reinterpret_cast<const uint2*>(&sm4[2048 + buf * 512]);
        const uint2* Br_ = reinterpret_cast<const uint2*>(&sm4[3072 + buf * 512]);
        #pragma unroll
        for (int kk = 0; kk < 4; kk++) {
            uint4 a0 = A_[(r0 * 4 + kk) * 32 + lane];
            uint4 a1 = A_[((r0 + 1) * 4 + kk) * 32 + lane];
            #pragma unroll
            for (int nt = 0; nt < 4; nt++) {
                uint2 bz = Bz_[(nbl + nt) * 128 + kk * 32 + lane];
                uint2 br = Br_[(nbl + nt) * 128 + kk * 32 + lane];
                mma16(accZ[0][nt], a0, bz);
                mma16(accZ[1][nt], a1, bz);
                mma16(accR[0][nt], a0, br);
                mma16(accR[1][nt], a1, br);
            }
        }
        __syncthreads();
    }

    // epilogue: z f32; rh fp16 fragment-ordered
    uint32_t* rhp32 = reinterpret_cast<uint32_t*>(g_rhp);
    const int wm = (wid & 3) * 32, wn = (wid >> 2) * 32;
    #pragma unroll
    for (int mt = 0; mt < 2; mt++) {
        const int rbase = bm + wm + mt * 16;
        #pragma unroll
        for (int nt = 0; nt < 4; nt++) {
            const int colb = bn + wn + nt * 8 + tq * 2;
            const int kb = ((bn + wn) >> 4) + (nt >> 1);
            #pragma unroll
            for (int half = 0; half < 2; half++) {
                const int row = rbase + half * 8 + g;
                const int idx = row * HH + colb;
                float2 hv = *reinterpret_cast<const float2*>(&h[idx]);
                float2 zo;
                zo.x = sig_(accZ[mt][nt][half * 2]);
                zo.y = sig_(accZ[mt][nt][half * 2 + 1]);
                *reinterpret_cast<float2*>(&g_Z[idx]) = zo;
                float rh0 = sig_(accR[mt][nt][half * 2]) * hv.x;
                float rh1 = sig_(accR[mt][nt][half * 2 + 1]) * hv.y;
                const int rbm = (rbase >> 4);
                const int regidx = half + 2 * (nt & 1);
                rhp32[((rbm * 64 + kb) * 32 + lane) * 4 + regidx] = h2u(rh0, rh1);
            }
        }
    }
}

// ---------------------------------------------------------------------------
// Kernel 2 (R8): block 128x64, 8 warps (4m x 2n), warp 32x32, BK=64.
// smem per buf (uint4): A[0,1024) B[1024,1536). 2 bufs = 48KB. 3 CTAs/SM.
// ---------------------------------------------------------------------------
__global__ void __launch_bounds__(256, 3) gemm_ht(const float* __restrict__ h,
                                                  float* __restrict__ out) {
    extern __shared__ uint4 sm4[];
    const int tid = threadIdx.x, wid = tid >> 5, lane = tid & 31;
    const int g = lane >> 2, tq = lane & 3;
    const int mrow = wid & 3, ncol = wid >> 2;   // 4 x 2 warps, warp 32x32
    const int bm = blockIdx.x * 128, bn = blockIdx.y * 64;
    const int rb0 = bm >> 4, nb0 = bn >> 3;

    auto stage = [&](int t, int buf) {
        const int seg = t >> 4, kb0 = (t & 15) * 4;
        const uint4* Ag = seg ? g_xp : g_rhp;
        const uint4* Bg = reinterpret_cast<const uint4*>(g_Wh[seg ? 5 : 4]);
        uint4* dst = &sm4[buf * 1536];
        #pragma unroll
        for (int i = 0; i < 4; i++) {
            int c = tid + i * 256, rbl = c >> 7, rem = c & 127;
            cp_async16(&dst[c], &Ag[((rb0 + rbl) * 64 + kb0) * 32 + rem]);
        }
        {
            int c = tid, nbl = c >> 6, rem = c & 63;
            cp_async16(&dst[1024 + c], &Bg[((nb0 + nbl) * 64 + kb0) * 16 + rem]);
            c = tid + 256; nbl = c >> 6; rem = c & 63;
            cp_async16(&dst[1024 + c], &Bg[((nb0 + nbl) * 64 + kb0) * 16 + rem]);
        }
        cp_commit();
    };

    float acc[2][4][4] = {};
    stage(0, 0);

    for (int t = 0; t < 32; t++) {
        cp_wait_all();
        __syncthreads();
        if (t + 1 < 32) stage(t + 1, (t + 1) & 1);
        const uint4* A_ = &sm4[(t & 1) * 1536];
        const uint2* B_ = reinterpret_cast<const uint2*>(&sm4[(t & 1) * 1536 + 1024]);
        #pragma unroll
        for (int kk = 0; kk < 4; kk++) {
            uint4 a0 = A_[((mrow * 2 + 0) * 4 + kk) * 32 + lane];
            uint4 a1 = A_[((mrow * 2 + 1) * 4 + kk) * 32 + lane];
            #pragma unroll
            for (int n = 0; n < 4; n++) {
                uint2 b = B_[((ncol * 4 + n) * 4 + kk) * 32 + lane];
                mma16(acc[0][n], a0, b);
                mma16(acc[1][n], a1, b);
            }
        }
        __syncthreads();
    }

    #pragma unroll
    for (int r = 0; r < 2; r++) {
        const int rowbase = bm + mrow * 32 + r * 16;
        #pragma unroll
        for (int n = 0; n < 4; n++) {
            const int col = bn + ncol * 32 + n * 8 + tq * 2;
            #pragma unroll
            for (int half = 0; half < 2; half++) {
                const int idx = (rowbase + half * 8 + g) * HH + col;
                float2 hv = *reinterpret_cast<const float2*>(&h[idx]);
                float2 zv = *reinterpret_cast<const float2*>(&g_Z[idx]);
                float2 ov;
                ov.x = zv.x * hv.x + (1.0f - zv.x) * ftanh_(acc[r][n][half * 2]);
                ov.y = zv.y * hv.y + (1.0f - zv.y) * ftanh_(acc[r][n][half * 2 + 1]);
                *reinterpret_cast<float2*>(&out[idx]) = ov;
            }
        }
    }
}

// ---------------------------------------------------------------------------
extern "C" void kernel_launch(void* const* d_in, const int* in_sizes, int n_in,
                              void* d_out, int out_size) {
    const float* x   = (const float*)d_in[0];
    const float* h   = (const float*)d_in[1];
    const float* Wwz = (const float*)d_in[2];
    const float* Wuz = (const float*)d_in[3];
    const float* Wwr = (const float*)d_in[4];
    const float* Wur = (const float*)d_in[5];
    const float* Wu  = (const float*)d_in[6];
    const float* Ww  = (const float*)d_in[7];
    float* out = (float*)d_out;

    const int s1 = 4096 * 16;   // 64 KB
    const int s2 = 3072 * 16;   // 48 KB
    cudaFuncSetAttribute(gemm_zr, cudaFuncAttributeMaxDynamicSharedMemorySize, s1);
    cudaFuncSetAttribute(gemm_ht, cudaFuncAttributeMaxDynamicSharedMemorySize, s2);

    permA<<<dim3(4096, 2), 256>>>(x, h);
    permB<<<dim3(1024, 6), 256>>>(Wwz, Wuz, Wwr, Wur, Wu, Ww);
    gemm_zr<<<dim3(64, 16), 256, s1>>>(h);
    gemm_ht<<<dim3(64, 16), 256, s2>>>(h, out);
}

// round 9
// speedup vs baseline: 1.2046x; 1.0075x over previous
#include <cuda_runtime.h>
#include <cuda_fp16.h>
#include <cstdint>

// GRU cell B=8192, I=H=1024 fp32. mma.sync fp16 m16n8k16 (fp32 accum).
// R9: 3-stage cp.async ring (wait_group 1 steady state, full drain at tail —
// the R6-validated pattern) at R8's occupancy (ht: 24 warps/SM, zr: 16).

#define BB 8192
#define HH 1024
#define KK 1024

// Fragment layouts (validated R4):
//  A: g_ap[((rb*64+kb)*32+lane)] = uint4{a0,a1,a2,a3}, lane=g*4+tq
//  B: g_Wh[w][((nb*64+kb)*32+lane)] = uint2{b0,b1}
__device__ __align__(16) uint4 g_xp[BB * KK / 8];
__device__ __align__(16) uint4 g_hp[BB * KK / 8];
__device__ __align__(16) uint4 g_rhp[BB * KK / 8];
__device__ __align__(16) float g_Z[BB * HH];
__device__ __align__(16) uint2 g_Wh[6][HH * KK / 4];  // 0:Wwz 1:Wuz 2:Wwr 3:Wur 4:Wu 5:Ww

__device__ __forceinline__ void cp_async16(void* sdst, const void* gsrc) {
    uint32_t s = (uint32_t)__cvta_generic_to_shared(sdst);
    asm volatile("cp.async.cg.shared.global [%0], [%1], 16;\n" :: "r"(s), "l"(gsrc));
}
__device__ __forceinline__ void cp_commit() { asm volatile("cp.async.commit_group;\n"); }
__device__ __forceinline__ void cp_wait1() { asm volatile("cp.async.wait_group 1;\n"); }
__device__ __forceinline__ void cp_wait0() { asm volatile("cp.async.wait_group 0;\n"); }

__device__ __forceinline__ void mma16(float c[4], const uint4& a, const uint2& b) {
    asm volatile(
        "mma.sync.aligned.m16n8k16.row.col.f32.f16.f16.f32 "
        "{%0,%1,%2,%3},{%4,%5,%6,%7},{%8,%9},{%0,%1,%2,%3};\n"
        : "+f"(c[0]), "+f"(c[1]), "+f"(c[2]), "+f"(c[3])
        : "r"(a.x), "r"(a.y), "r"(a.z), "r"(a.w), "r"(b.x), "r"(b.y));
}
__device__ __forceinline__ float sig_(float v) { return 1.0f / (1.0f + __expf(-v)); }
__device__ __forceinline__ float ftanh_(float v) {
    return 1.0f - 2.0f / (1.0f + __expf(2.0f * v));
}
__device__ __forceinline__ uint32_t h2u(float a, float b) {
    __half2 h = __floats2half2_rn(a, b);
    return *reinterpret_cast<uint32_t*>(&h);
}

// ---------------------------------------------------------------------------
// Preprocess (validated R4)
// ---------------------------------------------------------------------------
__global__ void __launch_bounds__(256) permA(const float* __restrict__ x,
                                             const float* __restrict__ hm) {
    const float* src = blockIdx.y ? hm : x;
    uint4* dst = blockIdx.y ? g_hp : g_xp;
    int t = blockIdx.x * 256 + threadIdx.x;
    int lane = t & 31, kb = (t >> 5) & 63, rb = t >> 11;
    int g = lane >> 2, tq = lane & 3;
    const float* s = src + (rb * 16 + g) * KK + kb * 16 + tq * 2;
    float2 v00 = *reinterpret_cast<const float2*>(s);
    float2 v10 = *reinterpret_cast<const float2*>(s + 8 * KK);
    float2 v01 = *reinterpret_cast<const float2*>(s + 8);
    float2 v11 = *reinterpret_cast<const float2*>(s + 8 * KK + 8);
    uint4 o;
    o.x = h2u(v00.x, v00.y);
    o.y = h2u(v10.x, v10.y);
    o.z = h2u(v01.x, v01.y);
    o.w = h2u(v11.x, v11.y);
    dst[t] = o;
}

__global__ void __launch_bounds__(256) permB(
    const float* __restrict__ w0, const float* __restrict__ w1,
    const float* __restrict__ w2, const float* __restrict__ w3,
    const float* __restrict__ w4, const float* __restrict__ w5) {
    const float* srcs[6] = {w0, w1, w2, w3, w4, w5};
    const float* src = srcs[blockIdx.y];
    uint2* dst = g_Wh[blockIdx.y];
    int t = blockIdx.x * 256 + threadIdx.x;
    int lane = t & 31, kb = (t >> 5) & 63, nb = t >> 11;
    int g = lane >> 2, tq = lane & 3;
    const float* s = src + (nb * 8 + g) * KK + kb * 16 + tq * 2;
    float2 v0 = *reinterpret_cast<const float2*>(s);
    float2 v1 = *reinterpret_cast<const float2*>(s + 8);
    uint2 o;
    o.x = h2u(v0.x, v0.y);
    o.y = h2u(v1.x, v1.y);
    dst[t] = o;
}

// ---------------------------------------------------------------------------
// Kernel 1: dual-acc z/r GEMM. Block 128x64, 8 warps (4m x 2n), warp 32x32
// dual, BK=64, 3-stage ring. smem/stage (uint4): A 1024 | Bz 512 | Br 512.
// 3 stages = 96KB, 2 CTAs/SM.
// ---------------------------------------------------------------------------
__global__ void __launch_bounds__(256, 2) gemm_zr(const float* __restrict__ h) {
    extern __shared__ uint4 sm4[];
    const int tid = threadIdx.x, wid = tid >> 5, lane = tid & 31;
    const int g = lane >> 2, tq = lane & 3;
    const int bm = blockIdx.x * 128, bn = blockIdx.y * 64;
    const int rb0 = bm >> 4, nb0 = bn >> 3;

    auto stage = [&](int t) {
        const int seg = t >> 4, kb = (t & 15) * 4;
        const uint4* Ag = seg ? g_hp : g_xp;
        const uint4* Bz = reinterpret_cast<const uint4*>(g_Wh[seg ? 1 : 0]);
        const uint4* Br = reinterpret_cast<const uint4*>(g_Wh[seg ? 3 : 2]);
        uint4* dst = &sm4[(t % 3) * 2048];
        #pragma unroll
        for (int i = 0; i < 4; i++) {
            int c = tid + i * 256, rbl = c >> 7, rem = c & 127;
            cp_async16(&dst[c], &Ag[((rb0 + rbl) * 64 + kb) * 32 + rem]);
        }
        #pragma unroll
        for (int i = 0; i < 2; i++) {
            int c = tid + i * 256, nbl = c >> 6, rem = c & 63;
            int so = ((nb0 + nbl) * 64 + kb) * 16 + rem;
            cp_async16(&dst[1024 + c], &Bz[so]);
            cp_async16(&dst[1536 + c], &Br[so]);
        }
        cp_commit();
    };

    float accZ[2][4][4] = {}, accR[2][4][4] = {};
    stage(0);
    stage(1);

    const int r0 = (wid & 3) * 2, nbl = (wid >> 2) * 4;
    for (int t = 0; t < 32; t++) {
        if (t + 2 < 32) cp_wait1(); else cp_wait0();
        __syncthreads();
        if (t + 2 < 32) stage(t + 2);
        const uint4* A_ = &sm4[(t % 3) * 2048];
        const uint2* Bz_ = reinterpret_cast<const uint2*>(&A_[1024]);
        const uint2* Br_ = reinterpret_cast<const uint2*>(&A_[1536]);
        #pragma unroll
        for (int kk = 0; kk < 4; kk++) {
            uint4 a0 = A_[(r0 * 4 + kk) * 32 + lane];
            uint4 a1 = A_[((r0 + 1) * 4 + kk) * 32 + lane];
            #pragma unroll
            for (int nt = 0; nt < 4; nt++) {
                uint2 bz = Bz_[(nbl + nt) * 128 + kk * 32 + lane];
                uint2 br = Br_[(nbl + nt) * 128 + kk * 32 + lane];
                mma16(accZ[0][nt], a0, bz);
                mma16(accZ[1][nt], a1, bz);
                mma16(accR[0][nt], a0, br);
                mma16(accR[1][nt], a1, br);
            }
        }
    }

    // epilogue: z f32; rh fp16 fragment-ordered (validated R4)
    uint32_t* rhp32 = reinterpret_cast<uint32_t*>(g_rhp);
    const int wm = (wid & 3) * 32, wn = (wid >> 2) * 32;
    #pragma unroll
    for (int mt = 0; mt < 2; mt++) {
        const int rbase = bm + wm + mt * 16;
        #pragma unroll
        for (int nt = 0; nt < 4; nt++) {
            const int colb = bn + wn + nt * 8 + tq * 2;
            const int kb = ((bn + wn) >> 4) + (nt >> 1);
            #pragma unroll
            for (int half = 0; half < 2; half++) {
                const int row = rbase + half * 8 + g;
                const int idx = row * HH + colb;
                float2 hv = *reinterpret_cast<const float2*>(&h[idx]);
                float2 zo;
                zo.x = sig_(accZ[mt][nt][half * 2]);
                zo.y = sig_(accZ[mt][nt][half * 2 + 1]);
                *reinterpret_cast<float2*>(&g_Z[idx]) = zo;
                float rh0 = sig_(accR[mt][nt][half * 2]) * hv.x;
                float rh1 = sig_(accR[mt][nt][half * 2 + 1]) * hv.y;
                const int rbm = (rbase >> 4);
                const int regidx = half + 2 * (nt & 1);
                rhp32[((rbm * 64 + kb) * 32 + lane) * 4 + regidx] = h2u(rh0, rh1);
            }
        }
    }
}

// ---------------------------------------------------------------------------
// Kernel 2: block 128x64, 8 warps (4m x 2n), warp 32x32, BK=64, 3-stage ring.
// smem/stage (uint4): A 1024 | B 512. 3 stages = 72KB, 3 CTAs/SM.
// ---------------------------------------------------------------------------
__global__ void __launch_bounds__(256, 3) gemm_ht(const float* __restrict__ h,
                                                  float* __restrict__ out) {
    extern __shared__ uint4 sm4[];
    const int tid = threadIdx.x, wid = tid >> 5, lane = tid & 31;
    const int g = lane >> 2, tq = lane & 3;
    const int mrow = wid & 3, ncol = wid >> 2;   // 4 x 2 warps, warp 32x32
    const int bm = blockIdx.x * 128, bn = blockIdx.y * 64;
    const int rb0 = bm >> 4, nb0 = bn >> 3;

    auto stage = [&](int t) {
        const int seg = t >> 4, kb0 = (t & 15) * 4;
        const uint4* Ag = seg ? g_xp : g_rhp;
        const uint4* Bg = reinterpret_cast<const uint4*>(g_Wh[seg ? 5 : 4]);
        uint4* dst = &sm4[(t % 3) * 1536];
        #pragma unroll
        for (int i = 0; i < 4; i++) {
            int c = tid + i * 256, rbl = c >> 7, rem = c & 127;
            cp_async16(&dst[c], &Ag[((rb0 + rbl) * 64 + kb0) * 32 + rem]);
        }
        #pragma unroll
        for (int i = 0; i < 2; i++) {
            int c = tid + i * 256, nbl = c >> 6, rem = c & 63;
            cp_async16(&dst[1024 + c], &Bg[((nb0 + nbl) * 64 + kb0) * 16 + rem]);
        }
        cp_commit();
    };

    float acc[2][4][4] = {};
    stage(0);
    stage(1);

    for (int t = 0; t < 32; t++) {
        if (t + 2 < 32) cp_wait1(); else cp_wait0();
        __syncthreads();
        if (t + 2 < 32) stage(t + 2);
        const uint4* A_ = &sm4[(t % 3) * 1536];
        const uint2* B_ = reinterpret_cast<const uint2*>(&A_[1024]);
        #pragma unroll
        for (int kk = 0; kk < 4; kk++) {
            uint4 a0 = A_[((mrow * 2 + 0) * 4 + kk) * 32 + lane];
            uint4 a1 = A_[((mrow * 2 + 1) * 4 + kk) * 32 + lane];
            #pragma unroll
            for (int n = 0; n < 4; n++) {
                uint2 b = B_[((ncol * 4 + n) * 4 + kk) * 32 + lane];
                mma16(acc[0][n], a0, b);
                mma16(acc[1][n], a1, b);
            }
        }
    }

    #pragma unroll
    for (int r = 0; r < 2; r++) {
        const int rowbase = bm + mrow * 32 + r * 16;
        #pragma unroll
        for (int n = 0; n < 4; n++) {
            const int col = bn + ncol * 32 + n * 8 + tq * 2;
            #pragma unroll
            for (int half = 0; half < 2; half++) {
                const int idx = (rowbase + half * 8 + g) * HH + col;
                float2 hv = *reinterpret_cast<const float2*>(&h[idx]);
                float2 zv = *reinterpret_cast<const float2*>(&g_Z[idx]);
                float2 ov;
                ov.x = zv.x * hv.x + (1.0f - zv.x) * ftanh_(acc[r][n][half * 2]);
                ov.y = zv.y * hv.y + (1.0f - zv.y) * ftanh_(acc[r][n][half * 2 + 1]);
                *reinterpret_cast<float2*>(&out[idx]) = ov;
            }
        }
    }
}

// ---------------------------------------------------------------------------
extern "C" void kernel_launch(void* const* d_in, const int* in_sizes, int n_in,
                              void* d_out, int out_size) {
    const float* x   = (const float*)d_in[0];
    const float* h   = (const float*)d_in[1];
    const float* Wwz = (const float*)d_in[2];
    const float* Wuz = (const float*)d_in[3];
    const float* Wwr = (const float*)d_in[4];
    const float* Wur = (const float*)d_in[5];
    const float* Wu  = (const float*)d_in[6];
    const float* Ww  = (const float*)d_in[7];
    float* out = (float*)d_out;

    const int s1 = 6144 * 16;   // 96 KB
    const int s2 = 4608 * 16;   // 72 KB
    cudaFuncSetAttribute(gemm_zr, cudaFuncAttributeMaxDynamicSharedMemorySize, s1);
    cudaFuncSetAttribute(gemm_ht, cudaFuncAttributeMaxDynamicSharedMemorySize, s2);

    permA<<<dim3(4096, 2), 256>>>(x, h);
    permB<<<dim3(1024, 6), 256>>>(Wwz, Wuz, Wwr, Wur, Wu, Ww);
    gemm_zr<<<dim3(64, 16), 256, s1>>>(h);
    gemm_ht<<<dim3(64, 16), 256, s2>>>(h, out);
}